// round 10
// baseline (speedup 1.0000x reference)
#include <cuda_runtime.h>
#include <cstdint>

#define L 256
#define BB 16
#define NC 8
#define LL2 (L * L)
#define NEGF (-1000000000.0f)
#define TMAIN 1024
#define NCTA (BB * NC)
#define P 33

__device__ float  g_bS[BB * LL2];
__device__ float  g_bE[BB * LL2];
__device__ float  g_gS[BB * LL2];
__device__ float  g_gE[BB * LL2];
__device__ int    g_lens[BB];
__device__ double g_span[NCTA];
__device__ double g_b1[NCTA], g_b2[NCTA];
__device__ unsigned long long g_ctr;

#define CLUSTER_SYNC() do { \
    asm volatile("barrier.cluster.arrive.aligned;" ::: "memory"); \
    asm volatile("barrier.cluster.wait.aligned;"   ::: "memory"); } while (0)

template<int NCH, class F>
__device__ __forceinline__ void warp_lse_ms(int T, int lane, F f, float& M, float& S) {
    float vv[NCH]; float m = NEGF;
    #pragma unroll
    for (int k = 0; k < NCH; ++k) { int t = lane + k * 32; vv[k] = (t < T) ? f(t) : NEGF; m = fmaxf(m, vv[k]); }
    #pragma unroll
    for (int o = 16; o; o >>= 1) m = fmaxf(m, __shfl_xor_sync(0xffffffffu, m, o));
    float s = 0.f;
    #pragma unroll
    for (int k = 0; k < NCH; ++k) s += __expf(vv[k] - m);
    #pragma unroll
    for (int o = 16; o; o >>= 1) s += __shfl_xor_sync(0xffffffffu, s, o);
    M = m; S = s;
}

template<class F>
__device__ __forceinline__ void far_ms(int T, int lane, F f, float& M, float& S) {
    if      (T <= 32)  warp_lse_ms<1>(T, lane, f, M, S);
    else if (T <= 128) warp_lse_ms<4>(T, lane, f, M, S);
    else               warp_lse_ms<8>(T, lane, f, M, S);
}

// near-terms LSE merged with (mF,sF); result valid in all lanes
template<class F>
__device__ __forceinline__ float lse_near(int Tn, int lane, F f, float mF, float sF) {
    float v0 = (lane < Tn)      ? f(lane)      : NEGF;
    float v1 = (lane + 32 < Tn) ? f(lane + 32) : NEGF;
    float m = fmaxf(fmaxf(v0, v1), mF);
    #pragma unroll
    for (int o = 16; o; o >>= 1) m = fmaxf(m, __shfl_xor_sync(0xffffffffu, m, o));
    float s = __expf(v0 - m) + __expf(v1 - m);
    #pragma unroll
    for (int o = 16; o; o >>= 1) s += __shfl_xor_sync(0xffffffffu, s, o);
    s += sF * __expf(mF - m);
    return m + __logf(s);
}

__device__ __forceinline__ int robust_len(const unsigned char* __restrict__ maskspan, int b, int lane) {
    const unsigned char* rowb = maskspan + (size_t)b * LL2;
    int c8 = 0;
    for (int j = lane; j < L; j += 32) c8 += (rowb[j] != 0) ? 1 : 0;
    #pragma unroll
    for (int o = 16; o; o >>= 1) c8 += __shfl_xor_sync(0xffffffffu, c8, o);
    int n;
    if (c8 >= 100 && rowb[0] == 1) n = c8;
    else {
        const unsigned int* rowi = ((const unsigned int*)maskspan) + (size_t)b * LL2;
        int c32 = 0;
        for (int j = lane; j < L; j += 32) c32 += (rowi[j] != 0u) ? 1 : 0;
        #pragma unroll
        for (int o = 16; o; o >>= 1) c32 += __shfl_xor_sync(0xffffffffu, c32, o);
        n = c32;
    }
    return max(1, min(L, n));
}

__global__ void __launch_bounds__(TMAIN, 1)
main_kernel(const float* __restrict__ lg_all,
            const float* __restrict__ ph_all,  const float* __restrict__ pt_all,
            const float* __restrict__ pharc_all,
            const int* __restrict__ spans_all,
            const int* __restrict__ phind_all, const int* __restrict__ ptind_all,
            const unsigned char* __restrict__ maskspan,
            float* __restrict__ out) {
    __shared__ float sWin[63 * P];
    __shared__ float sSlab1[94 * P];
    __shared__ float sSlab2[63 * P];
    __shared__ float sMm[2016], sSs[2016];
    __shared__ double sh_red[32];
    __shared__ int sh_n, sh_last;

    const int cb = blockIdx.x, b = cb >> 3, rank = cb & 7;
    const int tid = threadIdx.x, lane = tid & 31, wid = tid >> 5;
    const int r0 = rank * 32;

    if (wid == 0) {
        int nn = robust_len(maskspan, b, lane);
        if (lane == 0) { sh_n = nn; if (rank == 0) g_lens[b] = nn; }
    }
    __syncthreads();
    const int n = sh_n;
    const int nsteps = (n + 31) >> 5;

    const float* __restrict__ lg    = lg_all    + (size_t)b * LL2;
    const float* __restrict__ pharc = pharc_all + (size_t)b * LL2;
    const int*   __restrict__ spans = spans_all + (size_t)b * LL2;
    float* __restrict__ bS = g_bS + (size_t)b * LL2;
    float* __restrict__ bE = g_bE + (size_t)b * LL2;
    float* __restrict__ gS = g_gS + (size_t)b * LL2;
    float* __restrict__ gE = g_gE + (size_t)b * LL2;

    double accT = 0.0;

    // ======================= INSIDE =======================
    for (int s = 0; s < nsteps; ++s) {
        const int w0 = s * 32;
        if (s == 0) {
            for (int ri = tid; ri < 63; ri += TMAIN) {
                int i = r0 + ri;
                if (i < n) sWin[ri * P] = __ldg(&lg[i * L + i]);
            }
            __syncthreads();
            for (int wo = 1; wo < 32; ++wo) {
                #pragma unroll
                for (int rr = 0; rr < 2; ++rr) {
                    int ri = wid + rr * 32;
                    if (ri < 63) {
                        int i = r0 + ri;
                        if (i + wo < n && (ri < 32 || ri + wo <= 62)) {
                            auto f = [&](int t) { return sWin[ri * P + t] + sWin[(ri + t + 1) * P + (wo - t - 1)]; };
                            float res = lse_near(wo, lane, f, NEGF, 0.f) + __ldg(&lg[i * L + i + wo]);
                            if (lane == 0) sWin[ri * P + wo] = res;
                        }
                    }
                }
                __syncthreads();
            }
        } else {
            for (int idx = tid; idx < 63 * 32; idx += TMAIN) {
                int rr = idx >> 5, c = idx & 31;
                int gA = r0 + w0 + 1 + rr;
                sSlab1[rr * P + c] = (gA < n) ? __ldcg(&bS[gA * L + c]) : NEGF;
                int gB = r0 + rr;
                sSlab2[rr * P + c] = (gB < n) ? __ldcg(&bS[gB * L + c]) : NEGF;
            }
            for (int cell = wid; cell < 2016; cell += 32) {
                int ri = cell >> 5, wo = cell & 31;
                int i = r0 + ri, w = w0 + wo;
                float M = NEGF, S = 0.f;
                if (i + w < n && (ri < 32 || ri + wo <= 62)) {
                    const float* Lr = bS + (size_t)i * L + (w - w0);
                    const float* Rr = bE + (size_t)(i + w) * L + (w0 - 1);
                    auto f = [&](int q) { return __ldcg(Lr + q) + __ldcg(Rr - q); };
                    far_ms(2 * w0 - w, lane, f, M, S);
                }
                if (lane == 0) { sMm[cell] = M; sSs[cell] = S; }
            }
            __syncthreads();
            for (int wo = 0; wo < 32; ++wo) {
                int w = w0 + wo;
                #pragma unroll
                for (int rr = 0; rr < 2; ++rr) {
                    int ri = wid + rr * 32;
                    if (ri < 63) {
                        int i = r0 + ri;
                        if (i + w < n && (ri < 32 || ri + wo <= 62)) {
                            int cell = ri * 32 + wo;
                            auto f = [&](int t)->float {
                                if (t < wo) return sWin[ri * P + t] + sSlab1[(ri + t) * P + (wo - t - 1)];
                                int u = t - wo;
                                return sSlab2[ri * P + u] + sWin[(ri + u + 1) * P + (wo - u - 1)];
                            };
                            float res = lse_near(2 * wo, lane, f, sMm[cell], sSs[cell]) + __ldg(&lg[i * L + i + w]);
                            if (lane == 0) sWin[ri * P + wo] = res;
                        }
                    }
                }
                __syncthreads();
            }
        }
        {   // write owned rows
            int ri = tid >> 5, wo = tid & 31;
            int i = r0 + ri, w = w0 + wo;
            if (i + w < n) {
                float v = sWin[ri * P + wo];
                __stcg(&bS[i * L + w], v);
                __stcg(&bE[(i + w) * L + w], v);
            }
        }
        CLUSTER_SYNC();
    }

    const float logZ = __ldcg(&bS[n - 1]);

    // ======================= OUTSIDE =======================
    for (int s = nsteps - 1; s >= 0; --s) {
        const int w1 = s * 32;
        for (int idx = tid; idx < 94 * 32; idx += TMAIN) {
            int rr = idx >> 5, c = idx & 31;
            int g1 = r0 + w1 - 30 + rr;
            sSlab1[rr * P + c] = (g1 >= 0 && g1 < n) ? __ldcg(&bS[g1 * L + c]) : NEGF;
            if (rr < 63) {
                int g2 = r0 - 32 + rr;
                sSlab2[rr * P + c] = (g2 >= 0 && g2 < n) ? __ldcg(&bE[g2 * L + c]) : NEGF;
            }
        }
        for (int cell = wid; cell < 2016; cell += 32) {
            int ri = cell >> 5, wo = cell & 31;
            int a = r0 - 31 + ri, w = w1 + wo, bj = a + w;
            float M = NEGF, S = 0.f;
            if (a >= 0 && bj < n && (ri >= 31 || ri + wo >= 31)) {
                int c1f = max(0, n - a - w1 - 32);
                int c2f = max(0, a + w - w1 - 31);
                const float* P1a = gS + (size_t)a * L + (w1 + 32);
                const float* P1b = bS + (size_t)(bj + 1) * L + (w1 + 31 - w);
                const float* P2a = gE + (size_t)bj * L + (w1 + 32);
                const float* P2b = bE + (size_t)(a - 1) * L + (w1 + 31 - w);
                auto f = [&](int q) {
                    if (q < c1f) return __ldcg(P1a + q) + __ldcg(P1b + q);
                    int q2 = q - c1f;
                    return __ldcg(P2a + q2) + __ldcg(P2b + q2);
                };
                far_ms(c1f + c2f, lane, f, M, S);
            }
            if (lane == 0) { sMm[cell] = M; sSs[cell] = S; }
        }
        __syncthreads();
        for (int wo = 31; wo >= 0; --wo) {
            int w = w1 + wo;
            #pragma unroll
            for (int rr = 0; rr < 2; ++rr) {
                int ri = wid + rr * 32;
                if (ri < 63) {
                    int a = r0 - 31 + ri, bj = a + w;
                    if (a >= 0 && bj < n && (ri >= 31 || ri + wo >= 31)) {
                        int T1n = max(0, min(31 - wo, n - 1 - bj));
                        int T2n = min(31 - wo, a);
                        int cell = ri * 32 + wo;
                        auto f = [&](int t)->float {
                            if (t < T1n) return sWin[ri * P + wo + t + 1] + sSlab1[(ri + wo) * P + t];
                            int k = t - T1n + 1;
                            return sWin[(ri - k) * P + (wo + k)] + sSlab2[ri * P + (k - 1)];
                        };
                        float mF = sMm[cell], sF = sSs[cell];
                        float al = lse_near(T1n + T2n, lane, f, mF, sF);
                        int c1f = max(0, n - a - w1 - 32);
                        int c2f = max(0, a + w - w1 - 31);
                        if (T1n + T2n + c1f + c2f == 0) al = 0.f;     // root
                        if (lane == 0) sWin[ri * P + wo] = al + __ldg(&lg[a * L + bj]);
                    }
                }
            }
            __syncthreads();
        }
        {   // write owned + fused loss
            int ro = tid >> 5, wo = tid & 31;
            int a = r0 + ro, w = w1 + wo, bj = a + w;
            if (a < n && bj < n) {
                float gv = sWin[(ro + 31) * P + wo];
                __stcg(&gS[a * L + w], gv);
                __stcg(&gE[bj * L + w], gv);
                float lgv = __ldg(&lg[a * L + bj]);
                float mu = fminf(__expf((gv - lgv) + __ldcg(&bS[a * L + w]) - logZ), 1.0f);
                float p  = 1.f / (1.f + __expf(-__ldg(&pharc[a * L + bj])));
                float pm = p * mu;
                accT += (__ldg(&spans[a * L + bj]) >= 2) ? (double)__logf(pm) : (double)log1pf(-pm);
            }
        }
        CLUSTER_SYNC();
    }

    // ======================= BCE slice =======================
    float f1 = 0.f, f2 = 0.f;
    {
        const float* __restrict__ ph    = ph_all    + (size_t)b * LL2;
        const float* __restrict__ pt    = pt_all    + (size_t)b * LL2;
        const int*   __restrict__ phind = phind_all + (size_t)b * LL2;
        const int*   __restrict__ ptind = ptind_all + (size_t)b * LL2;
        for (int idx = rank * TMAIN + tid; idx < n * L; idx += NC * TMAIN) {
            int j = idx & (L - 1);
            if (j < n) {
                float x = __ldg(&ph[idx]);
                f1 += fmaxf(x, 0.f) + log1pf(__expf(-fabsf(x))) - x * (float)__ldg(&phind[idx]);
                float y = __ldg(&pt[idx]);
                f2 += fmaxf(y, 0.f) + log1pf(__expf(-fabsf(y))) - y * (float)__ldg(&ptind[idx]);
            }
        }
    }

    double acc = accT;
    #pragma unroll
    for (int o = 16; o; o >>= 1) {
        acc += __shfl_down_sync(0xffffffffu, acc, o);
        f1  += __shfl_down_sync(0xffffffffu, f1, o);
        f2  += __shfl_down_sync(0xffffffffu, f2, o);
    }
    if (lane == 0) sh_red[wid] = acc;
    __syncthreads();
    if (wid == 0) {
        double v = sh_red[lane];
        #pragma unroll
        for (int o = 16; o; o >>= 1) v += __shfl_down_sync(0xffffffffu, v, o);
        if (lane == 0) g_span[cb] = v;
    }
    __syncthreads();
    if (lane == 0) sh_red[wid] = (double)f1;
    __syncthreads();
    if (wid == 0) {
        double v = sh_red[lane];
        #pragma unroll
        for (int o = 16; o; o >>= 1) v += __shfl_down_sync(0xffffffffu, v, o);
        if (lane == 0) g_b1[cb] = v;
    }
    __syncthreads();
    if (lane == 0) sh_red[wid] = (double)f2;
    __syncthreads();
    if (wid == 0) {
        double v = sh_red[lane];
        #pragma unroll
        for (int o = 16; o; o >>= 1) v += __shfl_down_sync(0xffffffffu, v, o);
        if (lane == 0) g_b2[cb] = v;
    }
    __syncthreads();

    if (tid == 0) {
        __threadfence();
        unsigned long long old = atomicAdd(&g_ctr, 1ULL);
        sh_last = ((old % (unsigned long long)NCTA) == (unsigned long long)(NCTA - 1)) ? 1 : 0;
        if (sh_last) __threadfence();
    }
    __syncthreads();
    if (sh_last && wid == 0) {
        double span = 0.0, b1 = 0.0, b2 = 0.0;
        for (int k = lane; k < NCTA; k += 32) {
            span += *((volatile double*)&g_span[k]);
            b1   += *((volatile double*)&g_b1[k]);
            b2   += *((volatile double*)&g_b2[k]);
        }
        #pragma unroll
        for (int o = 16; o; o >>= 1) {
            span += __shfl_down_sync(0xffffffffu, span, o);
            b1   += __shfl_down_sync(0xffffffffu, b1, o);
            b2   += __shfl_down_sync(0xffffffffu, b2, o);
        }
        if (lane == 0) {
            double lsum = 0.0, sq = 0.0;
            for (int bb = 0; bb < BB; ++bb) {
                double nn = (double)(*((volatile int*)&g_lens[bb]));
                lsum += nn; sq += nn * nn;
            }
            double loss = 0.1 * (-span / lsum) + 0.9 * (b1 / sq + b2 / sq);
            out[0] = (float)loss;
        }
    }
}

extern "C" void kernel_launch(void* const* d_in, const int* in_sizes, int n_in,
                              void* d_out, int out_size) {
    const float* span_logits = (const float*)d_in[0];
    const float* ph          = (const float*)d_in[1];
    const float* pt          = (const float*)d_in[2];
    const float* ph_arc      = (const float*)d_in[3];
    const int*   spans_ind   = (const int*)d_in[4];
    const int*   ph_ind      = (const int*)d_in[5];
    const int*   pt_ind      = (const int*)d_in[6];
    const unsigned char* maskspan = (const unsigned char*)d_in[8];
    (void)in_sizes; (void)n_in; (void)out_size;

    cudaLaunchConfig_t cfg = {};
    cfg.gridDim  = dim3(NCTA, 1, 1);
    cfg.blockDim = dim3(TMAIN, 1, 1);
    cfg.dynamicSmemBytes = 0;
    cfg.stream = 0;
    cudaLaunchAttribute attrs[1];
    attrs[0].id = cudaLaunchAttributeClusterDimension;
    attrs[0].val.clusterDim.x = NC;
    attrs[0].val.clusterDim.y = 1;
    attrs[0].val.clusterDim.z = 1;
    cfg.attrs = attrs;
    cfg.numAttrs = 1;
    cudaLaunchKernelEx(&cfg, main_kernel,
                       span_logits, ph, pt, ph_arc, spans_ind, ph_ind, pt_ind, maskspan,
                       (float*)d_out);
}

// round 11
// speedup vs baseline: 1.1154x; 1.1154x over previous
#include <cuda_runtime.h>
#include <cstdint>

#define L 256
#define BB 16
#define NC 8
#define LL2 (L * L)
#define NEGF (-1000000000.0f)
#define TMAIN 1024
#define NCTA (BB * NC)
#define P 34   // pitch: anti-diagonal delta P-1=33 ≡ 1 (mod 32) -> conflict-free

__device__ float  g_bS[BB * LL2];
__device__ float  g_bE[BB * LL2];
__device__ float  g_gS[BB * LL2];
__device__ float  g_gE[BB * LL2];
__device__ int    g_lens[BB];
__device__ double g_span[NCTA];
__device__ double g_b1[NCTA], g_b2[NCTA];
__device__ unsigned long long g_ctr;

#define CLUSTER_SYNC() do { \
    asm volatile("barrier.cluster.arrive.aligned;" ::: "memory"); \
    asm volatile("barrier.cluster.wait.aligned;"   ::: "memory"); } while (0)

template<int NCH, class F>
__device__ __forceinline__ void warp_lse_ms(int T, int lane, F f, float& M, float& S) {
    float vv[NCH]; float m = NEGF;
    #pragma unroll
    for (int k = 0; k < NCH; ++k) { int t = lane + k * 32; vv[k] = (t < T) ? f(t) : NEGF; m = fmaxf(m, vv[k]); }
    #pragma unroll
    for (int o = 16; o; o >>= 1) m = fmaxf(m, __shfl_xor_sync(0xffffffffu, m, o));
    float s = 0.f;
    #pragma unroll
    for (int k = 0; k < NCH; ++k) s += __expf(vv[k] - m);
    #pragma unroll
    for (int o = 16; o; o >>= 1) s += __shfl_xor_sync(0xffffffffu, s, o);
    M = m; S = s;
}

template<class F>
__device__ __forceinline__ void far_ms(int T, int lane, F f, float& M, float& S) {
    if      (T <= 32)  warp_lse_ms<1>(T, lane, f, M, S);
    else if (T <= 128) warp_lse_ms<4>(T, lane, f, M, S);
    else               warp_lse_ms<8>(T, lane, f, M, S);
}

// near-terms LSE merged with (mF,sF); result valid in all lanes
template<class F>
__device__ __forceinline__ float lse_near(int Tn, int lane, F f, float mF, float sF) {
    float v0 = (lane < Tn)      ? f(lane)      : NEGF;
    float v1 = (lane + 32 < Tn) ? f(lane + 32) : NEGF;
    float m = fmaxf(fmaxf(v0, v1), mF);
    #pragma unroll
    for (int o = 16; o; o >>= 1) m = fmaxf(m, __shfl_xor_sync(0xffffffffu, m, o));
    float s = __expf(v0 - m) + __expf(v1 - m);
    #pragma unroll
    for (int o = 16; o; o >>= 1) s += __shfl_xor_sync(0xffffffffu, s, o);
    s += sF * __expf(mF - m);
    return m + __logf(s);
}

__device__ __forceinline__ int robust_len(const unsigned char* __restrict__ maskspan, int b, int lane) {
    const unsigned char* rowb = maskspan + (size_t)b * LL2;
    int c8 = 0;
    for (int j = lane; j < L; j += 32) c8 += (rowb[j] != 0) ? 1 : 0;
    #pragma unroll
    for (int o = 16; o; o >>= 1) c8 += __shfl_xor_sync(0xffffffffu, c8, o);
    int n;
    if (c8 >= 100 && rowb[0] == 1) n = c8;
    else {
        const unsigned int* rowi = ((const unsigned int*)maskspan) + (size_t)b * LL2;
        int c32 = 0;
        for (int j = lane; j < L; j += 32) c32 += (rowi[j] != 0u) ? 1 : 0;
        #pragma unroll
        for (int o = 16; o; o >>= 1) c32 += __shfl_xor_sync(0xffffffffu, c32, o);
        n = c32;
    }
    return max(1, min(L, n));
}

__global__ void __launch_bounds__(TMAIN, 1)
main_kernel(const float* __restrict__ lg_all,
            const float* __restrict__ ph_all,  const float* __restrict__ pt_all,
            const float* __restrict__ pharc_all,
            const int* __restrict__ spans_all,
            const int* __restrict__ phind_all, const int* __restrict__ ptind_all,
            const unsigned char* __restrict__ maskspan,
            float* __restrict__ out) {
    __shared__ float sWin[63 * P];
    __shared__ float sSlab1[94 * P];
    __shared__ float sSlab2[63 * P];
    __shared__ float sMm[2016], sSs[2016];
    __shared__ double sh_red[32];
    __shared__ int sh_n, sh_last;

    const int cb = blockIdx.x, b = cb >> 3, rank = cb & 7;
    const int tid = threadIdx.x, lane = tid & 31, wid = tid >> 5;
    const int r0 = rank * 32;

    if (wid == 0) {
        int nn = robust_len(maskspan, b, lane);
        if (lane == 0) { sh_n = nn; if (rank == 0) g_lens[b] = nn; }
    }
    __syncthreads();
    const int n = sh_n;
    const int nsteps = (n + 31) >> 5;

    const float* __restrict__ lg    = lg_all    + (size_t)b * LL2;
    const float* __restrict__ pharc = pharc_all + (size_t)b * LL2;
    const int*   __restrict__ spans = spans_all + (size_t)b * LL2;
    float* __restrict__ bS = g_bS + (size_t)b * LL2;
    float* __restrict__ bE = g_bE + (size_t)b * LL2;
    float* __restrict__ gS = g_gS + (size_t)b * LL2;
    float* __restrict__ gE = g_gE + (size_t)b * LL2;

    double accT = 0.0;

    // ======================= INSIDE =======================
    for (int s = 0; s < nsteps; ++s) {
        const int w0 = s * 32;
        if (s == 0) {
            for (int ri = tid; ri < 63; ri += TMAIN) {
                int i = r0 + ri;
                if (i < n) sWin[ri * P] = __ldg(&lg[i * L + i]);
            }
            __syncthreads();
            for (int wo = 1; wo < 32; ++wo) {
                #pragma unroll
                for (int rr = 0; rr < 2; ++rr) {
                    int ri = wid + rr * 32;
                    if (ri < 63) {
                        int i = r0 + ri;
                        if (i + wo < n && (ri < 32 || ri + wo <= 62)) {
                            auto f = [&](int t) { return sWin[ri * P + t] + sWin[(ri + t + 1) * P + (wo - t - 1)]; };
                            float res = lse_near(wo, lane, f, NEGF, 0.f) + __ldg(&lg[i * L + i + wo]);
                            if (lane == 0) sWin[ri * P + wo] = res;
                        }
                    }
                }
                __syncthreads();
            }
        } else {
            for (int idx = tid; idx < 63 * 32; idx += TMAIN) {
                int rr = idx >> 5, c = idx & 31;
                int gA = r0 + w0 + 1 + rr;
                sSlab1[rr * P + c] = (gA < n) ? __ldcg(&bS[gA * L + c]) : NEGF;
                int gB = r0 + rr;
                sSlab2[rr * P + c] = (gB < n) ? __ldcg(&bS[gB * L + c]) : NEGF;
            }
            for (int cell = wid; cell < 2016; cell += 32) {
                int ri = cell >> 5, wo = cell & 31;
                int i = r0 + ri, w = w0 + wo;
                float M = NEGF, S = 0.f;
                if (i + w < n && (ri < 32 || ri + wo <= 62)) {
                    const float* Lr = bS + (size_t)i * L + (w - w0);
                    const float* Rr = bE + (size_t)(i + w) * L + (w0 - 1);
                    auto f = [&](int q) { return __ldcg(Lr + q) + __ldcg(Rr - q); };
                    far_ms(2 * w0 - w, lane, f, M, S);
                }
                if (lane == 0) { sMm[cell] = M; sSs[cell] = S; }
            }
            __syncthreads();
            for (int wo = 0; wo < 32; ++wo) {
                int w = w0 + wo;
                #pragma unroll
                for (int rr = 0; rr < 2; ++rr) {
                    int ri = wid + rr * 32;
                    if (ri < 63) {
                        int i = r0 + ri;
                        if (i + w < n && (ri < 32 || ri + wo <= 62)) {
                            int cell = ri * 32 + wo;
                            auto f = [&](int t)->float {
                                if (t < wo) return sWin[ri * P + t] + sSlab1[(ri + t) * P + (wo - t - 1)];
                                int u = t - wo;
                                return sSlab2[ri * P + u] + sWin[(ri + u + 1) * P + (wo - u - 1)];
                            };
                            float res = lse_near(2 * wo, lane, f, sMm[cell], sSs[cell]) + __ldg(&lg[i * L + i + w]);
                            if (lane == 0) sWin[ri * P + wo] = res;
                        }
                    }
                }
                __syncthreads();
            }
        }
        {   // write owned rows
            int ri = tid >> 5, wo = tid & 31;
            int i = r0 + ri, w = w0 + wo;
            if (i + w < n) {
                float v = sWin[ri * P + wo];
                __stcg(&bS[i * L + w], v);
                __stcg(&bE[(i + w) * L + w], v);
            }
        }
        CLUSTER_SYNC();
    }

    const float logZ = __ldcg(&bS[n - 1]);

    // ======================= OUTSIDE =======================
    for (int s = nsteps - 1; s >= 0; --s) {
        const int w1 = s * 32;
        for (int idx = tid; idx < 94 * 32; idx += TMAIN) {
            int rr = idx >> 5, c = idx & 31;
            int g1 = r0 + w1 - 30 + rr;
            sSlab1[rr * P + c] = (g1 >= 0 && g1 < n) ? __ldcg(&bS[g1 * L + c]) : NEGF;
            if (rr < 63) {
                int g2 = r0 - 32 + rr;
                sSlab2[rr * P + c] = (g2 >= 0 && g2 < n) ? __ldcg(&bE[g2 * L + c]) : NEGF;
            }
        }
        for (int cell = wid; cell < 2016; cell += 32) {
            int ri = cell >> 5, wo = cell & 31;
            int a = r0 - 31 + ri, w = w1 + wo, bj = a + w;
            float M = NEGF, S = 0.f;
            if (a >= 0 && bj < n && (ri >= 31 || ri + wo >= 31)) {
                int c1f = max(0, n - a - w1 - 32);
                int c2f = max(0, a + w - w1 - 31);
                const float* P1a = gS + (size_t)a * L + (w1 + 32);
                const float* P1b = bS + (size_t)(bj + 1) * L + (w1 + 31 - w);
                const float* P2a = gE + (size_t)bj * L + (w1 + 32);
                const float* P2b = bE + (size_t)(a - 1) * L + (w1 + 31 - w);
                auto f = [&](int q) {
                    if (q < c1f) return __ldcg(P1a + q) + __ldcg(P1b + q);
                    int q2 = q - c1f;
                    return __ldcg(P2a + q2) + __ldcg(P2b + q2);
                };
                far_ms(c1f + c2f, lane, f, M, S);
            }
            if (lane == 0) { sMm[cell] = M; sSs[cell] = S; }
        }
        __syncthreads();
        for (int wo = 31; wo >= 0; --wo) {
            int w = w1 + wo;
            #pragma unroll
            for (int rr = 0; rr < 2; ++rr) {
                int ri = wid + rr * 32;
                if (ri < 63) {
                    int a = r0 - 31 + ri, bj = a + w;
                    if (a >= 0 && bj < n && (ri >= 31 || ri + wo >= 31)) {
                        int T1n = max(0, min(31 - wo, n - 1 - bj));
                        int T2n = min(31 - wo, a);
                        int cell = ri * 32 + wo;
                        auto f = [&](int t)->float {
                            if (t < T1n) return sWin[ri * P + wo + t + 1] + sSlab1[(ri + wo) * P + t];
                            int k = t - T1n + 1;
                            return sWin[(ri - k) * P + (wo + k)] + sSlab2[ri * P + (k - 1)];
                        };
                        float mF = sMm[cell], sF = sSs[cell];
                        float al = lse_near(T1n + T2n, lane, f, mF, sF);
                        int c1f = max(0, n - a - w1 - 32);
                        int c2f = max(0, a + w - w1 - 31);
                        if (T1n + T2n + c1f + c2f == 0) al = 0.f;     // root
                        if (lane == 0) sWin[ri * P + wo] = al + __ldg(&lg[a * L + bj]);
                    }
                }
            }
            __syncthreads();
        }
        {   // write owned + fused loss
            int ro = tid >> 5, wo = tid & 31;
            int a = r0 + ro, w = w1 + wo, bj = a + w;
            if (a < n && bj < n) {
                float gv = sWin[(ro + 31) * P + wo];
                __stcg(&gS[a * L + w], gv);
                __stcg(&gE[bj * L + w], gv);
                float lgv = __ldg(&lg[a * L + bj]);
                float mu = fminf(__expf((gv - lgv) + __ldcg(&bS[a * L + w]) - logZ), 1.0f);
                float p  = 1.f / (1.f + __expf(-__ldg(&pharc[a * L + bj])));
                float pm = p * mu;
                accT += (__ldg(&spans[a * L + bj]) >= 2) ? (double)__logf(pm) : (double)log1pf(-pm);
            }
        }
        CLUSTER_SYNC();
    }

    // ======================= BCE slice =======================
    float f1 = 0.f, f2 = 0.f;
    {
        const float* __restrict__ ph    = ph_all    + (size_t)b * LL2;
        const float* __restrict__ pt    = pt_all    + (size_t)b * LL2;
        const int*   __restrict__ phind = phind_all + (size_t)b * LL2;
        const int*   __restrict__ ptind = ptind_all + (size_t)b * LL2;
        for (int idx = rank * TMAIN + tid; idx < n * L; idx += NC * TMAIN) {
            int j = idx & (L - 1);
            if (j < n) {
                float x = __ldg(&ph[idx]);
                f1 += fmaxf(x, 0.f) + log1pf(__expf(-fabsf(x))) - x * (float)__ldg(&phind[idx]);
                float y = __ldg(&pt[idx]);
                f2 += fmaxf(y, 0.f) + log1pf(__expf(-fabsf(y))) - y * (float)__ldg(&ptind[idx]);
            }
        }
    }

    double acc = accT;
    #pragma unroll
    for (int o = 16; o; o >>= 1) {
        acc += __shfl_down_sync(0xffffffffu, acc, o);
        f1  += __shfl_down_sync(0xffffffffu, f1, o);
        f2  += __shfl_down_sync(0xffffffffu, f2, o);
    }
    if (lane == 0) sh_red[wid] = acc;
    __syncthreads();
    if (wid == 0) {
        double v = sh_red[lane];
        #pragma unroll
        for (int o = 16; o; o >>= 1) v += __shfl_down_sync(0xffffffffu, v, o);
        if (lane == 0) g_span[cb] = v;
    }
    __syncthreads();
    if (lane == 0) sh_red[wid] = (double)f1;
    __syncthreads();
    if (wid == 0) {
        double v = sh_red[lane];
        #pragma unroll
        for (int o = 16; o; o >>= 1) v += __shfl_down_sync(0xffffffffu, v, o);
        if (lane == 0) g_b1[cb] = v;
    }
    __syncthreads();
    if (lane == 0) sh_red[wid] = (double)f2;
    __syncthreads();
    if (wid == 0) {
        double v = sh_red[lane];
        #pragma unroll
        for (int o = 16; o; o >>= 1) v += __shfl_down_sync(0xffffffffu, v, o);
        if (lane == 0) g_b2[cb] = v;
    }
    __syncthreads();

    if (tid == 0) {
        __threadfence();
        unsigned long long old = atomicAdd(&g_ctr, 1ULL);
        sh_last = ((old % (unsigned long long)NCTA) == (unsigned long long)(NCTA - 1)) ? 1 : 0;
        if (sh_last) __threadfence();
    }
    __syncthreads();
    if (sh_last && wid == 0) {
        double span = 0.0, b1 = 0.0, b2 = 0.0;
        for (int k = lane; k < NCTA; k += 32) {
            span += *((volatile double*)&g_span[k]);
            b1   += *((volatile double*)&g_b1[k]);
            b2   += *((volatile double*)&g_b2[k]);
        }
        #pragma unroll
        for (int o = 16; o; o >>= 1) {
            span += __shfl_down_sync(0xffffffffu, span, o);
            b1   += __shfl_down_sync(0xffffffffu, b1, o);
            b2   += __shfl_down_sync(0xffffffffu, b2, o);
        }
        if (lane == 0) {
            double lsum = 0.0, sq = 0.0;
            for (int bb = 0; bb < BB; ++bb) {
                double nn = (double)(*((volatile int*)&g_lens[bb]));
                lsum += nn; sq += nn * nn;
            }
            double loss = 0.1 * (-span / lsum) + 0.9 * (b1 / sq + b2 / sq);
            out[0] = (float)loss;
        }
    }
}

extern "C" void kernel_launch(void* const* d_in, const int* in_sizes, int n_in,
                              void* d_out, int out_size) {
    const float* span_logits = (const float*)d_in[0];
    const float* ph          = (const float*)d_in[1];
    const float* pt          = (const float*)d_in[2];
    const float* ph_arc      = (const float*)d_in[3];
    const int*   spans_ind   = (const int*)d_in[4];
    const int*   ph_ind      = (const int*)d_in[5];
    const int*   pt_ind      = (const int*)d_in[6];
    const unsigned char* maskspan = (const unsigned char*)d_in[8];
    (void)in_sizes; (void)n_in; (void)out_size;

    cudaLaunchConfig_t cfg = {};
    cfg.gridDim  = dim3(NCTA, 1, 1);
    cfg.blockDim = dim3(TMAIN, 1, 1);
    cfg.dynamicSmemBytes = 0;
    cfg.stream = 0;
    cudaLaunchAttribute attrs[1];
    attrs[0].id = cudaLaunchAttributeClusterDimension;
    attrs[0].val.clusterDim.x = NC;
    attrs[0].val.clusterDim.y = 1;
    attrs[0].val.clusterDim.z = 1;
    cfg.attrs = attrs;
    cfg.numAttrs = 1;
    cudaLaunchKernelEx(&cfg, main_kernel,
                       span_logits, ph, pt, ph_arc, spans_ind, ph_ind, pt_ind, maskspan,
                       (float*)d_out);
}

// round 13
// speedup vs baseline: 1.4561x; 1.3055x over previous
#include <cuda_runtime.h>
#include <cstdint>

#define L 256
#define BB 16
#define NC 8
#define LL2 (L * L)
#define NEGF (-1000000000.0f)
#define TMAIN 1024
#define NCTA (BB * NC)
#define P 33

// dynamic smem layout (floats)
#define OFF_WIN 0                 // 63*P = 2079
#define OFF_S1  2079              // 94*P = 3102
#define OFF_S2  5181              // 63*P = 2079
#define OFF_LG  7260              // 63*P = 2079
#define OFF_M   9339              // 2048
#define OFF_SS  11387             // 2048
#define SM_FLOATS 13435
#define SMEM_BYTES (SM_FLOATS * 4)

__device__ float  g_bS[BB * LL2];
__device__ float  g_bE[BB * LL2];
__device__ float  g_gS[BB * LL2];
__device__ float  g_gE[BB * LL2];
__device__ int    g_lens[BB];
__device__ double g_span[NCTA];
__device__ double g_b1[NCTA], g_b2[NCTA];
__device__ unsigned long long g_ctr;

#define CLUSTER_SYNC() do { \
    asm volatile("barrier.cluster.arrive.aligned;" ::: "memory"); \
    asm volatile("barrier.cluster.wait.aligned;"   ::: "memory"); } while (0)

// warp max of f32 via order-preserving s32 bijection + redux.sync.max.s32 (sm_80+)
__device__ __forceinline__ float rmax_redux(float x) {
    int k = __float_as_int(x);
    k = (k < 0) ? (k ^ 0x7FFFFFFF) : k;
    int r;
    asm volatile("redux.sync.max.s32 %0, %1, 0xffffffff;" : "=r"(r) : "r"(k));
    r = (r < 0) ? (r ^ 0x7FFFFFFF) : r;
    return __int_as_float(r);
}

// 1-exp online LSE update: exp(-|v-m|) serves both branches
__device__ __forceinline__ void lse1(float& m, float& s, float v) {
    float d = v - m;
    float e = __expf(-fabsf(d));
    s = (d <= 0.f) ? (s + e) : fmaf(s, e, 1.f);
    m = fmaxf(m, v);
}

template<int NCH, class F>
__device__ __forceinline__ void warp_lse_ms(int T, int lane, F f, float& M, float& S) {
    float vv[NCH]; float m = NEGF;
    #pragma unroll
    for (int k = 0; k < NCH; ++k) { int t = lane + k * 32; vv[k] = (t < T) ? f(t) : NEGF; m = fmaxf(m, vv[k]); }
    m = rmax_redux(m);
    float s = 0.f;
    #pragma unroll
    for (int k = 0; k < NCH; ++k) s += __expf(vv[k] - m);
    #pragma unroll
    for (int o = 16; o; o >>= 1) s += __shfl_xor_sync(0xffffffffu, s, o);
    M = m; S = s;
}

template<class F>
__device__ __forceinline__ void far_ms(int T, int lane, F f, float& M, float& S) {
    if      (T <= 32)  warp_lse_ms<1>(T, lane, f, M, S);
    else if (T <= 128) warp_lse_ms<4>(T, lane, f, M, S);
    else               warp_lse_ms<8>(T, lane, f, M, S);
}

__device__ __forceinline__ int robust_len(const unsigned char* __restrict__ maskspan, int b, int lane) {
    const unsigned char* rowb = maskspan + (size_t)b * LL2;
    int c8 = 0;
    for (int j = lane; j < L; j += 32) c8 += (rowb[j] != 0) ? 1 : 0;
    #pragma unroll
    for (int o = 16; o; o >>= 1) c8 += __shfl_xor_sync(0xffffffffu, c8, o);
    int n;
    if (c8 >= 100 && rowb[0] == 1) n = c8;
    else {
        const unsigned int* rowi = ((const unsigned int*)maskspan) + (size_t)b * LL2;
        int c32 = 0;
        for (int j = lane; j < L; j += 32) c32 += (rowi[j] != 0u) ? 1 : 0;
        #pragma unroll
        for (int o = 16; o; o >>= 1) c32 += __shfl_xor_sync(0xffffffffu, c32, o);
        n = c32;
    }
    return max(1, min(L, n));
}

__global__ void __launch_bounds__(TMAIN, 1)
main_kernel(const float* __restrict__ lg_all,
            const float* __restrict__ ph_all,  const float* __restrict__ pt_all,
            const float* __restrict__ pharc_all,
            const int* __restrict__ spans_all,
            const int* __restrict__ phind_all, const int* __restrict__ ptind_all,
            const unsigned char* __restrict__ maskspan,
            float* __restrict__ out) {
    extern __shared__ float sm[];
    float* sWin   = sm + OFF_WIN;
    float* sSlab1 = sm + OFF_S1;
    float* sSlab2 = sm + OFF_S2;
    float* sLg    = sm + OFF_LG;
    float* sMm    = sm + OFF_M;
    float* sSs    = sm + OFF_SS;
    __shared__ double sh_red[32];
    __shared__ int sh_n, sh_last;

    const int cb = blockIdx.x, b = cb >> 3, rank = cb & 7;
    const int tid = threadIdx.x, lane = tid & 31, wid = tid >> 5;
    const int r0 = rank * 32;

    if (wid == 0) {
        int nn = robust_len(maskspan, b, lane);
        if (lane == 0) { sh_n = nn; if (rank == 0) g_lens[b] = nn; }
    }
    __syncthreads();
    const int n = sh_n;
    const int nsteps = (n + 31) >> 5;

    const float* __restrict__ lg    = lg_all    + (size_t)b * LL2;
    const float* __restrict__ pharc = pharc_all + (size_t)b * LL2;
    const int*   __restrict__ spans = spans_all + (size_t)b * LL2;
    float* __restrict__ bS = g_bS + (size_t)b * LL2;
    float* __restrict__ bE = g_bE + (size_t)b * LL2;
    float* __restrict__ gS = g_gS + (size_t)b * LL2;
    float* __restrict__ gE = g_gE + (size_t)b * LL2;

    double accT = 0.0;

    // ======================= INSIDE =======================
    for (int s = 0; s < nsteps; ++s) {
        const int w0 = s * 32;
        // lg window tile
        for (int idx = tid; idx < 63 * 32; idx += TMAIN) {
            int ri = idx >> 5, wo = idx & 31;
            int i = r0 + ri, j = i + w0 + wo;
            sLg[ri * P + wo] = (i < n && j < n) ? __ldg(&lg[i * L + j]) : 0.f;
        }
        if (s > 0) {
            for (int idx = tid; idx < 63 * 32; idx += TMAIN) {
                int rr = idx >> 5, c = idx & 31;
                int gA = r0 + w0 + 1 + rr;
                sSlab1[rr * P + c] = (gA < n) ? __ldcg(&bS[gA * L + c]) : NEGF;
                int gB = r0 + rr;
                sSlab2[rr * P + c] = (gB < n) ? __ldcg(&bS[gB * L + c]) : NEGF;
            }
            // far phase (warp per cell)
            for (int cell = wid; cell < 2016; cell += 32) {
                int ri = cell >> 5, wo = cell & 31;
                int i = r0 + ri, w = w0 + wo;
                float M = NEGF, S = 0.f;
                if (i + w < n && (ri < 32 || ri + wo <= 62)) {
                    const float* Lr = bS + (size_t)i * L + (w - w0);
                    const float* Rr = bE + (size_t)(i + w) * L + (w0 - 1);
                    auto f = [&](int q) { return __ldcg(Lr + q) + __ldcg(Rr - q); };
                    far_ms(2 * w0 - w, lane, f, M, S);
                }
                if (lane == 0) { sMm[cell] = M; sSs[cell] = S; }
            }
        }
        __syncthreads();

        // near phase: thread-per-cell (2 cells/thread), lanes = wo
        {
            const int riA = tid >> 5, riB = riA + 32, wo = lane;
            const int iA = r0 + riA, iB = r0 + riB;
            const bool actA = (iA + w0 + wo < n);                      // riA<32 always
            const bool actB = (iB + w0 + wo < n) && (riB + wo <= 62);
            float mA, sA2, mB, sB2;
            if (s == 0) { mA = NEGF; sA2 = 0.f; mB = NEGF; sB2 = 0.f; }
            else { mA = sMm[tid]; sA2 = sSs[tid]; mB = sMm[tid + 1024]; sB2 = sSs[tid + 1024]; }

            for (int u = 0; u < 32; ++u) {
                if (lane == u) {
                    if (actA) sWin[riA * P + u] = (s == 0 && u == 0) ? sLg[riA * P]
                                                : (mA + __logf(sA2) + sLg[riA * P + u]);
                    if (actB) sWin[riB * P + u] = (s == 0 && u == 0) ? sLg[riB * P]
                                                : (mB + __logf(sB2) + sLg[riB * P + u]);
                }
                __syncthreads();
                if (u < 31) {
                    if (s == 0) {
                        if (actA && wo > u) {
                            if (2 * u >= wo - 1) lse1(mA, sA2, sWin[riA * P + u] + sWin[(riA + u + 1) * P + (wo - u - 1)]);
                            if (2 * u >  wo - 1) lse1(mA, sA2, sWin[riA * P + (wo - 1 - u)] + sWin[(riA + wo - u) * P + u]);
                        }
                        if (actB && wo > u) {
                            if (2 * u >= wo - 1) lse1(mB, sB2, sWin[riB * P + u] + sWin[(riB + u + 1) * P + (wo - u - 1)]);
                            if (2 * u >  wo - 1) lse1(mB, sB2, sWin[riB * P + (wo - 1 - u)] + sWin[(riB + wo - u) * P + u]);
                        }
                    } else {
                        if (actA && wo > u) {
                            lse1(mA, sA2, sWin[riA * P + u] + sSlab1[(riA + u) * P + (wo - u - 1)]);
                            lse1(mA, sA2, sSlab2[riA * P + (wo - u - 1)] + sWin[(riA + wo - u) * P + u]);
                        }
                        if (actB && wo > u) {
                            lse1(mB, sB2, sWin[riB * P + u] + sSlab1[(riB + u) * P + (wo - u - 1)]);
                            lse1(mB, sB2, sSlab2[riB * P + (wo - u - 1)] + sWin[(riB + wo - u) * P + u]);
                        }
                    }
                    __syncthreads();
                }
            }
        }
        {   // write owned rows
            int ri = tid >> 5, wo = tid & 31;
            int i = r0 + ri, w = w0 + wo;
            if (i + w < n) {
                float v = sWin[ri * P + wo];
                __stcg(&bS[i * L + w], v);
                __stcg(&bE[(i + w) * L + w], v);
            }
        }
        CLUSTER_SYNC();
    }

    const float logZ = __ldcg(&bS[n - 1]);

    // ======================= OUTSIDE =======================
    for (int s = nsteps - 1; s >= 0; --s) {
        const int w1 = s * 32;
        // lg tile for this window (rows ri = 0..62 -> a = r0-31+ri)
        for (int idx = tid; idx < 63 * 32; idx += TMAIN) {
            int ri = idx >> 5, wo = idx & 31;
            int a = r0 - 31 + ri, bj = a + w1 + wo;
            sLg[ri * P + wo] = (a >= 0 && bj >= 0 && bj < n) ? __ldg(&lg[a * L + bj]) : 0.f;
        }
        for (int idx = tid; idx < 94 * 32; idx += TMAIN) {
            int rr = idx >> 5, c = idx & 31;
            int g1 = r0 + w1 - 30 + rr;
            sSlab1[rr * P + c] = (g1 >= 0 && g1 < n) ? __ldcg(&bS[g1 * L + c]) : NEGF;
            if (rr < 63) {
                int g2 = r0 - 32 + rr;
                sSlab2[rr * P + c] = (g2 >= 0 && g2 < n) ? __ldcg(&bE[g2 * L + c]) : NEGF;
            }
        }
        // far phase (warp per cell); handoff stored transposed: sMm[wo*64+ri]
        for (int cell = wid; cell < 2016; cell += 32) {
            int ri = cell >> 5, wo = cell & 31;
            int a = r0 - 31 + ri, w = w1 + wo, bj = a + w;
            float M = NEGF, S = 0.f;
            if (a >= 0 && bj < n && (ri >= 31 || ri + wo >= 31)) {
                int c1f = max(0, n - a - w1 - 32);
                int c2f = max(0, a + w - w1 - 31);
                const float* P1a = gS + (size_t)a * L + (w1 + 32);
                const float* P1b = bS + (size_t)(bj + 1) * L + (w1 + 31 - w);
                const float* P2a = gE + (size_t)bj * L + (w1 + 32);
                const float* P2b = bE + (size_t)(a - 1) * L + (w1 + 31 - w);
                auto f = [&](int q) {
                    if (q < c1f) return __ldcg(P1a + q) + __ldcg(P1b + q);
                    int q2 = q - c1f;
                    return __ldcg(P2a + q2) + __ldcg(P2b + q2);
                };
                far_ms(c1f + c2f, lane, f, M, S);
            }
            if (lane == 0) { sMm[wo * 64 + ri] = M; sSs[wo * 64 + ri] = S; }
        }
        __syncthreads();

        // near phase: thread-per-cell, lanes = ri (cells padded to wo*64+ri)
        {
            const int woA = tid >> 6, woB = woA + 16;
            const int ri  = tid & 63;
            const int a   = r0 - 31 + ri;
            const int bjA = a + w1 + woA, bjB = a + w1 + woB;
            const bool actA = (ri < 63) && (a >= 0) && (bjA < n) && (ri >= 31 || ri + woA >= 31);
            const bool actB = (ri < 63) && (a >= 0) && (bjB < n) && (ri >= 31 || ri + woB >= 31);
            const int T1A = actA ? max(0, min(31 - woA, n - 1 - bjA)) : 0;
            const int T2A = actA ? min(31 - woA, a) : 0;
            const int T1B = actB ? max(0, min(31 - woB, n - 1 - bjB)) : 0;
            const int T2B = actB ? min(31 - woB, a) : 0;
            float mA = sMm[tid], sA2 = sSs[tid];
            float mB = sMm[tid + 1024], sB2 = sSs[tid + 1024];

            for (int u = 31; u >= 0; --u) {
                if (woA == u && actA) {
                    float al = (a == 0 && bjA == n - 1) ? 0.f : (mA + __logf(sA2));
                    sWin[ri * P + u] = al + sLg[ri * P + u];
                }
                if (woB == u && actB) {
                    float al = (a == 0 && bjB == n - 1) ? 0.f : (mB + __logf(sB2));
                    sWin[ri * P + u] = al + sLg[ri * P + u];
                }
                __syncthreads();
                if (u > 0) {
                    if (actA && woA < u) {
                        int t1 = u - woA - 1;
                        if (t1 < T1A) lse1(mA, sA2, sWin[ri * P + u] + sSlab1[(ri + woA) * P + t1]);
                        int k = u - woA;
                        if (k <= T2A) lse1(mA, sA2, sWin[(ri - k) * P + u] + sSlab2[ri * P + (k - 1)]);
                    }
                    if (actB && woB < u) {
                        int t1 = u - woB - 1;
                        if (t1 < T1B) lse1(mB, sB2, sWin[ri * P + u] + sSlab1[(ri + woB) * P + t1]);
                        int k = u - woB;
                        if (k <= T2B) lse1(mB, sB2, sWin[(ri - k) * P + u] + sSlab2[ri * P + (k - 1)]);
                    }
                    __syncthreads();
                }
            }
        }
        {   // write owned + fused loss
            int ro = tid >> 5, wo = tid & 31;
            int a = r0 + ro, w = w1 + wo, bj = a + w;
            if (a < n && bj < n) {
                float gv = sWin[(ro + 31) * P + wo];
                __stcg(&gS[a * L + w], gv);
                __stcg(&gE[bj * L + w], gv);
                float lgv = sLg[(ro + 31) * P + wo];
                float mu = fminf(__expf((gv - lgv) + __ldcg(&bS[a * L + w]) - logZ), 1.0f);
                float p  = 1.f / (1.f + __expf(-__ldg(&pharc[a * L + bj])));
                float pm = p * mu;
                accT += (__ldg(&spans[a * L + bj]) >= 2) ? (double)__logf(pm) : (double)log1pf(-pm);
            }
        }
        CLUSTER_SYNC();
    }

    // ======================= BCE slice =======================
    float f1 = 0.f, f2 = 0.f;
    {
        const float* __restrict__ ph    = ph_all    + (size_t)b * LL2;
        const float* __restrict__ pt    = pt_all    + (size_t)b * LL2;
        const int*   __restrict__ phind = phind_all + (size_t)b * LL2;
        const int*   __restrict__ ptind = ptind_all + (size_t)b * LL2;
        for (int idx = rank * TMAIN + tid; idx < n * L; idx += NC * TMAIN) {
            int j = idx & (L - 1);
            if (j < n) {
                float x = __ldg(&ph[idx]);
                f1 += fmaxf(x, 0.f) + log1pf(__expf(-fabsf(x))) - x * (float)__ldg(&phind[idx]);
                float y = __ldg(&pt[idx]);
                f2 += fmaxf(y, 0.f) + log1pf(__expf(-fabsf(y))) - y * (float)__ldg(&ptind[idx]);
            }
        }
    }

    double acc = accT;
    #pragma unroll
    for (int o = 16; o; o >>= 1) {
        acc += __shfl_down_sync(0xffffffffu, acc, o);
        f1  += __shfl_down_sync(0xffffffffu, f1, o);
        f2  += __shfl_down_sync(0xffffffffu, f2, o);
    }
    if (lane == 0) sh_red[wid] = acc;
    __syncthreads();
    if (wid == 0) {
        double v = sh_red[lane];
        #pragma unroll
        for (int o = 16; o; o >>= 1) v += __shfl_down_sync(0xffffffffu, v, o);
        if (lane == 0) g_span[cb] = v;
    }
    __syncthreads();
    if (lane == 0) sh_red[wid] = (double)f1;
    __syncthreads();
    if (wid == 0) {
        double v = sh_red[lane];
        #pragma unroll
        for (int o = 16; o; o >>= 1) v += __shfl_down_sync(0xffffffffu, v, o);
        if (lane == 0) g_b1[cb] = v;
    }
    __syncthreads();
    if (lane == 0) sh_red[wid] = (double)f2;
    __syncthreads();
    if (wid == 0) {
        double v = sh_red[lane];
        #pragma unroll
        for (int o = 16; o; o >>= 1) v += __shfl_down_sync(0xffffffffu, v, o);
        if (lane == 0) g_b2[cb] = v;
    }
    __syncthreads();

    if (tid == 0) {
        __threadfence();
        unsigned long long old = atomicAdd(&g_ctr, 1ULL);
        sh_last = ((old % (unsigned long long)NCTA) == (unsigned long long)(NCTA - 1)) ? 1 : 0;
        if (sh_last) __threadfence();
    }
    __syncthreads();
    if (sh_last && wid == 0) {
        double span = 0.0, b1 = 0.0, b2 = 0.0;
        for (int k = lane; k < NCTA; k += 32) {
            span += *((volatile double*)&g_span[k]);
            b1   += *((volatile double*)&g_b1[k]);
            b2   += *((volatile double*)&g_b2[k]);
        }
        #pragma unroll
        for (int o = 16; o; o >>= 1) {
            span += __shfl_down_sync(0xffffffffu, span, o);
            b1   += __shfl_down_sync(0xffffffffu, b1, o);
            b2   += __shfl_down_sync(0xffffffffu, b2, o);
        }
        if (lane == 0) {
            double lsum = 0.0, sq = 0.0;
            for (int bb = 0; bb < BB; ++bb) {
                double nn = (double)(*((volatile int*)&g_lens[bb]));
                lsum += nn; sq += nn * nn;
            }
            double loss = 0.1 * (-span / lsum) + 0.9 * (b1 / sq + b2 / sq);
            out[0] = (float)loss;
        }
    }
}

extern "C" void kernel_launch(void* const* d_in, const int* in_sizes, int n_in,
                              void* d_out, int out_size) {
    const float* span_logits = (const float*)d_in[0];
    const float* ph          = (const float*)d_in[1];
    const float* pt          = (const float*)d_in[2];
    const float* ph_arc      = (const float*)d_in[3];
    const int*   spans_ind   = (const int*)d_in[4];
    const int*   ph_ind      = (const int*)d_in[5];
    const int*   pt_ind      = (const int*)d_in[6];
    const unsigned char* maskspan = (const unsigned char*)d_in[8];
    (void)in_sizes; (void)n_in; (void)out_size;

    cudaFuncSetAttribute(main_kernel, cudaFuncAttributeMaxDynamicSharedMemorySize, SMEM_BYTES);

    cudaLaunchConfig_t cfg = {};
    cfg.gridDim  = dim3(NCTA, 1, 1);
    cfg.blockDim = dim3(TMAIN, 1, 1);
    cfg.dynamicSmemBytes = SMEM_BYTES;
    cfg.stream = 0;
    cudaLaunchAttribute attrs[1];
    attrs[0].id = cudaLaunchAttributeClusterDimension;
    attrs[0].val.clusterDim.x = NC;
    attrs[0].val.clusterDim.y = 1;
    attrs[0].val.clusterDim.z = 1;
    cfg.attrs = attrs;
    cfg.numAttrs = 1;
    cudaLaunchKernelEx(&cfg, main_kernel,
                       span_logits, ph, pt, ph_arc, spans_ind, ph_ind, pt_ind, maskspan,
                       (float*)d_out);
}